// round 2
// baseline (speedup 1.0000x reference)
#include <cuda_runtime.h>
#include <math.h>

#define B_  32
#define L_  4096
#define D_  1024
#define NA_ 8
#define NCHUNK 16
#define LCHUNK (L_ / NCHUNK)   // 256

// Partial sums per (b, l-chunk, action, d). 32*16*8*1024 floats = 16.8 MB scratch.
__device__ float g_part[B_ * NCHUNK * NA_ * D_];

// ---------------------------------------------------------------------------
// Kernel 1: masked segmented sum of embeddings into per-chunk partials.
// grid = (NCHUNK, B), block = 256 threads. Each thread owns 4 consecutive
// D-columns (one float4). Action index is uniform across the block for each
// row l, so the 8-way branch is non-divergent.
//
// NOTE: mask is a bool array upcast by the harness to a 4-byte type
// (int32 or float32). Reading the 32-bit word and testing != 0 is correct
// for both encodings (True = 1 or 0x3F800000; False = 0 in both).
// ---------------------------------------------------------------------------
__global__ __launch_bounds__(256, 4)
void accum_kernel(const float* __restrict__ emb,
                  const int* __restrict__ actions,
                  const int* __restrict__ mask)
{
    const int chunk = blockIdx.x;
    const int b     = blockIdx.y;
    const int tid   = threadIdx.x;
    const int l0    = chunk * LCHUNK;

    __shared__ int s_act[LCHUNK];
    for (int i = tid; i < LCHUNK; i += 256) {
        int a = actions[b * L_ + l0 + i];
        int m = mask[b * L_ + l0 + i];        // 32-bit word, nonzero = True
        s_act[i] = (m != 0) ? a : -1;         // -1 = masked out
    }
    __syncthreads();

    float4 a0 = make_float4(0.f, 0.f, 0.f, 0.f);
    float4 a1 = a0, a2 = a0, a3 = a0, a4 = a0, a5 = a0, a6 = a0, a7 = a0;

    const float4* ep = reinterpret_cast<const float4*>(emb)
                       + (size_t)b * L_ * (D_ / 4)
                       + (size_t)l0 * (D_ / 4)
                       + tid;               // tid covers d4 = tid (4 floats)

    #pragma unroll 4
    for (int i = 0; i < LCHUNK; ++i) {
        const int act = s_act[i];           // uniform across block
        const float4 v = ep[(size_t)i * (D_ / 4)];
        if      (act == 0) { a0.x += v.x; a0.y += v.y; a0.z += v.z; a0.w += v.w; }
        else if (act == 1) { a1.x += v.x; a1.y += v.y; a1.z += v.z; a1.w += v.w; }
        else if (act == 2) { a2.x += v.x; a2.y += v.y; a2.z += v.z; a2.w += v.w; }
        else if (act == 3) { a3.x += v.x; a3.y += v.y; a3.z += v.z; a3.w += v.w; }
        else if (act == 4) { a4.x += v.x; a4.y += v.y; a4.z += v.z; a4.w += v.w; }
        else if (act == 5) { a5.x += v.x; a5.y += v.y; a5.z += v.z; a5.w += v.w; }
        else if (act == 6) { a6.x += v.x; a6.y += v.y; a6.z += v.z; a6.w += v.w; }
        else if (act == 7) { a7.x += v.x; a7.y += v.y; a7.z += v.z; a7.w += v.w; }
    }

    // Store 8 action-partials (fully overwritten => no zero-init needed).
    float4* out = reinterpret_cast<float4*>(g_part)
                  + ((size_t)(b * NCHUNK + chunk) * NA_) * (D_ / 4);
    out[0 * (D_ / 4) + tid] = a0;
    out[1 * (D_ / 4) + tid] = a1;
    out[2 * (D_ / 4) + tid] = a2;
    out[3 * (D_ / 4) + tid] = a3;
    out[4 * (D_ / 4) + tid] = a4;
    out[5 * (D_ / 4) + tid] = a5;
    out[6 * (D_ / 4) + tid] = a6;
    out[7 * (D_ / 4) + tid] = a7;
}

// ---------------------------------------------------------------------------
// Kernel 2: reduce partials -> feats, compute counts, both MLPs, softmax,
// sigmoid, and write all 6 outputs. grid = (NA, B), block = 128 threads.
// ---------------------------------------------------------------------------
__global__ __launch_bounds__(128)
void head_kernel(const int* __restrict__ actions,
                 const int* __restrict__ mask,
                 const float* __restrict__ sw1, const float* __restrict__ sb1,
                 const float* __restrict__ sw2, const float* __restrict__ sb2,
                 const float* __restrict__ ew1, const float* __restrict__ eb1,
                 const float* __restrict__ ew2, const float* __restrict__ eb2,
                 float* __restrict__ out)
{
    const int a   = blockIdx.x;
    const int b   = blockIdx.y;
    const int tid = threadIdx.x;

    __shared__ float s_feat[D_];
    __shared__ float s_h1[128];
    __shared__ float s_eh[64];
    __shared__ float s_logit[14];
    __shared__ float s_eff[3];
    __shared__ float s_red[128];
    __shared__ float s_cnt;

    // ---- count = sum_l mask * (action == a) ----
    int c = 0;
    for (int l = tid; l < L_; l += 128)
        c += (actions[b * L_ + l] == a && mask[b * L_ + l] != 0) ? 1 : 0;
    s_red[tid] = (float)c;
    __syncthreads();
    for (int s = 64; s > 0; s >>= 1) {
        if (tid < s) s_red[tid] += s_red[tid + s];
        __syncthreads();
    }
    if (tid == 0) s_cnt = s_red[0];
    __syncthreads();
    const float cnt      = s_cnt;
    const float inv_cnt  = 1.0f / fmaxf(cnt, 1.0f);
    const float seen     = (cnt > 0.0f) ? 1.0f : 0.0f;

    // ---- feats[d] = (sum over 16 chunk partials) / clip(cnt,1) ----
    #pragma unroll
    for (int k = 0; k < D_ / 128; ++k) {
        const int d = tid + k * 128;
        float s = 0.0f;
        #pragma unroll
        for (int ch = 0; ch < NCHUNK; ++ch)
            s += g_part[((size_t)(b * NCHUNK + ch) * NA_ + a) * D_ + d];
        s_feat[d] = s * inv_cnt;
    }
    __syncthreads();

    // ---- h1 = relu(feats @ sw1 + sb1), 128 outputs ----
    {
        float acc = sb1[tid];
        #pragma unroll 8
        for (int d = 0; d < D_; ++d)
            acc = fmaf(s_feat[d], sw1[d * 128 + tid], acc);
        s_h1[tid] = fmaxf(acc, 0.0f);
    }
    // ---- eh = relu(feats @ ew1 + eb1), 64 outputs ----
    if (tid < 64) {
        float acc = eb1[tid];
        #pragma unroll 8
        for (int d = 0; d < D_; ++d)
            acc = fmaf(s_feat[d], ew1[d * 64 + tid], acc);
        s_eh[tid] = fmaxf(acc, 0.0f);
    }
    __syncthreads();

    // ---- shift logits (14) and effects (3) ----
    if (tid < 14) {
        float acc = sb2[tid];
        #pragma unroll 8
        for (int k = 0; k < 128; ++k)
            acc = fmaf(s_h1[k], sw2[k * 14 + tid], acc);
        s_logit[tid] = acc;
    }
    if (tid >= 32 && tid < 35) {
        const int j = tid - 32;
        float acc = eb2[j];
        #pragma unroll 8
        for (int k = 0; k < 64; ++k)
            acc = fmaf(s_eh[k], ew2[k * 3 + j], acc);
        s_eff[j] = acc;
    }
    __syncthreads();

    // Output layout (flat float32, reference tuple order):
    //   [0,512)        shift            (B,8,2)
    //   [512,2304)     dx_logits        (B,8,7)
    //   [2304,4096)    dy_logits        (B,8,7)
    //   [4096,4352)    sigmoid(e0)*seen (B,8)
    //   [4352,4608)    sigmoid(e1)*seen (B,8)
    //   [4608,4864)    e2*seen          (B,8)
    const int ba = b * NA_ + a;

    if (tid < 7)              out[512  + ba * 7 + tid]       = s_logit[tid];
    if (tid >= 7 && tid < 14) out[2304 + ba * 7 + (tid - 7)] = s_logit[tid];

    if (tid == 0) {
        const float bins[7] = {-16.f, -8.f, -4.f, 0.f, 4.f, 8.f, 16.f};
        float shift[2];
        #pragma unroll
        for (int h = 0; h < 2; ++h) {
            const float* lg = &s_logit[h * 7];
            float mx = lg[0];
            #pragma unroll
            for (int j = 1; j < 7; ++j) mx = fmaxf(mx, lg[j]);
            float den = 0.0f, num = 0.0f;
            #pragma unroll
            for (int j = 0; j < 7; ++j) {
                const float e = __expf(lg[j] - mx);
                den += e;
                num += e * bins[j];
            }
            shift[h] = (num / den) * seen;
        }
        out[ba * 2 + 0] = shift[0];
        out[ba * 2 + 1] = shift[1];

        out[4096 + ba] = (1.0f / (1.0f + __expf(-s_eff[0]))) * seen;
        out[4352 + ba] = (1.0f / (1.0f + __expf(-s_eff[1]))) * seen;
        out[4608 + ba] = s_eff[2] * seen;
    }
}

// ---------------------------------------------------------------------------
extern "C" void kernel_launch(void* const* d_in, const int* in_sizes, int n_in,
                              void* d_out, int out_size)
{
    const float* emb  = (const float*)d_in[0];
    const int*   act  = (const int*)d_in[1];
    const int*   mask = (const int*)d_in[2];
    const float* sw1 = (const float*)d_in[3];
    const float* sb1 = (const float*)d_in[4];
    const float* sw2 = (const float*)d_in[5];
    const float* sb2 = (const float*)d_in[6];
    const float* ew1 = (const float*)d_in[7];
    const float* eb1 = (const float*)d_in[8];
    const float* ew2 = (const float*)d_in[9];
    const float* eb2 = (const float*)d_in[10];
    float* out = (float*)d_out;

    accum_kernel<<<dim3(NCHUNK, B_), 256>>>(emb, act, mask);
    head_kernel<<<dim3(NA_, B_), 128>>>(act, mask, sw1, sb1, sw2, sb2,
                                        ew1, eb1, ew2, eb2, out);
}

// round 3
// speedup vs baseline: 1.9563x; 1.9563x over previous
#include <cuda_runtime.h>
#include <math.h>

#define B_  32
#define L_  4096
#define D_  1024
#define D4_ (D_ / 4)           // 256 float4 per row
#define NA_ 8
#define NCHUNK 16
#define LCHUNK (L_ / NCHUNK)   // 256

// Partial sums per (b, l-chunk, action, d). 16.8 MB scratch.
__device__ float g_part[B_ * NCHUNK * NA_ * D_];
// Per (b, l-chunk, action) masked counts.
__device__ int   g_cnt [B_ * NCHUNK * NA_];

// ---------------------------------------------------------------------------
// Kernel 1: masked segmented sum into per-chunk partials.
// grid = (NCHUNK, B), 256 threads; thread owns one float4 column (d4 = tid).
// Rows are pre-grouped by action (deterministic ascending scan), so the main
// loop is branchless with one accumulator -> deep load batching.
// ---------------------------------------------------------------------------
__global__ __launch_bounds__(256, 4)
void accum_kernel(const float4* __restrict__ emb4,
                  const int* __restrict__ actions,
                  const int* __restrict__ mask)
{
    const int chunk = blockIdx.x;
    const int b     = blockIdx.y;
    const int tid   = threadIdx.x;
    const int l0    = chunk * LCHUNK;

    __shared__ int   s_act[LCHUNK];
    __shared__ short s_order[LCHUNK];
    __shared__ int   s_cnt[NA_];
    __shared__ int   s_start[NA_ + 1];

    {
        // mask is bool upcast to a 4-byte type by the harness; nonzero = True.
        int a = actions[b * L_ + l0 + tid];
        int m = mask[b * L_ + l0 + tid];
        s_act[tid] = (m != 0) ? a : -1;
    }
    __syncthreads();

    if (tid < NA_) {
        int c = 0;
        #pragma unroll 4
        for (int i = 0; i < LCHUNK; ++i) c += (s_act[i] == tid);
        s_cnt[tid] = c;
    }
    __syncthreads();
    if (tid == 0) {
        int acc = 0;
        #pragma unroll
        for (int a = 0; a < NA_; ++a) { s_start[a] = acc; acc += s_cnt[a]; }
        s_start[NA_] = acc;
    }
    __syncthreads();
    if (tid < NA_) {
        int pos = s_start[tid];
        for (int i = 0; i < LCHUNK; ++i)
            if (s_act[i] == tid) s_order[pos++] = (short)i;
        g_cnt[(b * NCHUNK + chunk) * NA_ + tid] = s_cnt[tid];
    }
    __syncthreads();

    const float4* base = emb4 + ((size_t)b * L_ + l0) * D4_ + tid;
    float4* outp = reinterpret_cast<float4*>(g_part)
                   + (size_t)(b * NCHUNK + chunk) * NA_ * D4_ + tid;

    #pragma unroll 1
    for (int a = 0; a < NA_; ++a) {
        float4 acc = make_float4(0.f, 0.f, 0.f, 0.f);
        const int s = s_start[a], e = s_start[a + 1];
        int i = s;
        for (; i + 4 <= e; i += 4) {
            const float4 v0 = base[(int)s_order[i]     * D4_];
            const float4 v1 = base[(int)s_order[i + 1] * D4_];
            const float4 v2 = base[(int)s_order[i + 2] * D4_];
            const float4 v3 = base[(int)s_order[i + 3] * D4_];
            acc.x += (v0.x + v1.x) + (v2.x + v3.x);
            acc.y += (v0.y + v1.y) + (v2.y + v3.y);
            acc.z += (v0.z + v1.z) + (v2.z + v3.z);
            acc.w += (v0.w + v1.w) + (v2.w + v3.w);
        }
        for (; i < e; ++i) {
            const float4 v = base[(int)s_order[i] * D4_];
            acc.x += v.x; acc.y += v.y; acc.z += v.z; acc.w += v.w;
        }
        outp[a * D4_] = acc;
    }
}

// ---------------------------------------------------------------------------
// Kernel 2: reduce partials -> feats, both MLPs, softmax, sigmoid, outputs.
// grid = (NA, B), 512 threads.
// ---------------------------------------------------------------------------
__global__ __launch_bounds__(512)
void head_kernel(const float* __restrict__ sw1, const float* __restrict__ sb1,
                 const float* __restrict__ sw2, const float* __restrict__ sb2,
                 const float* __restrict__ ew1, const float* __restrict__ eb1,
                 const float* __restrict__ ew2, const float* __restrict__ eb2,
                 float* __restrict__ out)
{
    const int a   = blockIdx.x;
    const int b   = blockIdx.y;
    const int tid = threadIdx.x;

    __shared__ float s_feat[D_];
    __shared__ float s_part[512];
    __shared__ float s_h1[128];
    __shared__ float s_eh[64];
    __shared__ float s_logit[14];
    __shared__ float s_eff[3];
    __shared__ float s_scal[2];   // [0] = inv_cnt, [1] = seen

    // ---- counts (from g_cnt) ----
    if (tid == 0) {
        int c = 0;
        #pragma unroll
        for (int ch = 0; ch < NCHUNK; ++ch)
            c += g_cnt[(b * NCHUNK + ch) * NA_ + a];
        s_scal[0] = 1.0f / fmaxf((float)c, 1.0f);
        s_scal[1] = (c > 0) ? 1.0f : 0.0f;
    }

    // ---- feats: each thread reduces 2 d-columns over 16 chunk partials ----
    float f0 = 0.f, f1 = 0.f;
    const float* gp = g_part + ((size_t)b * NCHUNK * NA_ + a) * D_;
    #pragma unroll
    for (int ch = 0; ch < NCHUNK; ++ch) {
        f0 += gp[(size_t)ch * NA_ * D_ + tid];
        f1 += gp[(size_t)ch * NA_ * D_ + tid + 512];
    }
    __syncthreads();           // s_scal ready
    const float inv_cnt = s_scal[0];
    const float seen    = s_scal[1];
    s_feat[tid]       = f0 * inv_cnt;
    s_feat[tid + 512] = f1 * inv_cnt;
    __syncthreads();

    // ---- MLP1 layer 1: 128 neurons, 4 threads each (coalesced sw1 reads) ----
    {
        const int n = tid & 127, g = tid >> 7;      // g in 0..3
        float acc = 0.f;
        #pragma unroll 8
        for (int i = 0; i < 256; ++i) {
            const int d = g * 256 + i;
            acc = fmaf(s_feat[d], sw1[d * 128 + n], acc);
        }
        s_part[tid] = acc;
    }
    __syncthreads();
    if (tid < 128) {
        float v = (s_part[tid] + s_part[128 + tid])
                + (s_part[256 + tid] + s_part[384 + tid]);
        s_h1[tid] = fmaxf(v + sb1[tid], 0.0f);
    }
    __syncthreads();

    // ---- effect MLP layer 1: 64 neurons, 8 threads each ----
    {
        const int n = tid & 63, g = tid >> 6;       // g in 0..7
        float acc = 0.f;
        #pragma unroll 8
        for (int i = 0; i < 128; ++i) {
            const int d = g * 128 + i;
            acc = fmaf(s_feat[d], ew1[d * 64 + n], acc);
        }
        s_part[tid] = acc;
    }
    __syncthreads();
    if (tid < 64) {
        float v = 0.f;
        #pragma unroll
        for (int g = 0; g < 8; ++g) v += s_part[g * 64 + tid];
        s_eh[tid] = fmaxf(v + eb1[tid], 0.0f);
    }
    __syncthreads();

    // ---- layer 2: warp-per-output ----
    {
        const int w = tid >> 5, lane = tid & 31;
        if (w < 14) {
            float acc = 0.f;
            #pragma unroll
            for (int k = lane; k < 128; k += 32)
                acc = fmaf(s_h1[k], sw2[k * 14 + w], acc);
            #pragma unroll
            for (int off = 16; off > 0; off >>= 1)
                acc += __shfl_down_sync(0xffffffffu, acc, off);
            if (lane == 0) s_logit[w] = acc + sb2[w];
        } else if (w == 14) {
            #pragma unroll
            for (int j = 0; j < 3; ++j) {
                float acc = fmaf(s_eh[lane], ew2[lane * 3 + j],
                                 s_eh[lane + 32] * ew2[(lane + 32) * 3 + j]);
                #pragma unroll
                for (int off = 16; off > 0; off >>= 1)
                    acc += __shfl_down_sync(0xffffffffu, acc, off);
                if (lane == 0) s_eff[j] = acc + eb2[j];
            }
        }
    }
    __syncthreads();

    // Output layout (flat float32, reference tuple order):
    //   [0,512)     shift (B,8,2)   [512,2304)  dx_logits (B,8,7)
    //   [2304,4096) dy_logits       [4096,4352) sig(e0)*seen
    //   [4352,4608) sig(e1)*seen    [4608,4864) e2*seen
    const int ba = b * NA_ + a;

    if (tid < 7)              out[512  + ba * 7 + tid]       = s_logit[tid];
    if (tid >= 7 && tid < 14) out[2304 + ba * 7 + (tid - 7)] = s_logit[tid];

    if (tid == 0) {
        const float bins[7] = {-16.f, -8.f, -4.f, 0.f, 4.f, 8.f, 16.f};
        #pragma unroll
        for (int h = 0; h < 2; ++h) {
            const float* lg = &s_logit[h * 7];
            float mx = lg[0];
            #pragma unroll
            for (int j = 1; j < 7; ++j) mx = fmaxf(mx, lg[j]);
            float den = 0.f, num = 0.f;
            #pragma unroll
            for (int j = 0; j < 7; ++j) {
                const float e = __expf(lg[j] - mx);
                den += e;
                num += e * bins[j];
            }
            out[ba * 2 + h] = (num / den) * seen;
        }
        out[4096 + ba] = (1.0f / (1.0f + __expf(-s_eff[0]))) * seen;
        out[4352 + ba] = (1.0f / (1.0f + __expf(-s_eff[1]))) * seen;
        out[4608 + ba] = s_eff[2] * seen;
    }
}

// ---------------------------------------------------------------------------
extern "C" void kernel_launch(void* const* d_in, const int* in_sizes, int n_in,
                              void* d_out, int out_size)
{
    const float4* emb4 = (const float4*)d_in[0];
    const int*    act  = (const int*)d_in[1];
    const int*    mask = (const int*)d_in[2];
    const float* sw1 = (const float*)d_in[3];
    const float* sb1 = (const float*)d_in[4];
    const float* sw2 = (const float*)d_in[5];
    const float* sb2 = (const float*)d_in[6];
    const float* ew1 = (const float*)d_in[7];
    const float* eb1 = (const float*)d_in[8];
    const float* ew2 = (const float*)d_in[9];
    const float* eb2 = (const float*)d_in[10];
    float* out = (float*)d_out;

    accum_kernel<<<dim3(NCHUNK, B_), 256>>>(emb4, act, mask);
    head_kernel<<<dim3(NA_, B_), 512>>>(sw1, sb1, sw2, sb2,
                                        ew1, eb1, ew2, eb2, out);
}